// round 5
// baseline (speedup 1.0000x reference)
#include <cuda_runtime.h>

// ConvLayer_6279242186805: submanifold sparse conv (K=27, P pairs/offset,
// Cin=Cout=32) + LeakyReLU + BatchNorm1d training-stats.
//
// R3: counting-sort contributions by (output-row-group, k) so each warp
// exclusively owns 32 output rows -> scatter becomes race-free smem RMW,
// eliminating the L2 fp32-atomic wall (216M element-adds) that bound R1/R2.

#define LRELU_SLOPE 0.01f
#define BN_EPS 1e-5f
#define CH 32
#define RPW 32                 // output rows owned per warp
#define N_MAX (1 << 20)        // max rows (actual 500K)
#define NBUCK_MAX (1 << 20)    // max buckets = (N_MAX/32)*K(27) = 884736
#define NP_MAX (1 << 23)       // max total contributions (actual 6.75M)
#define CHUNK 1024

__device__ int g_cursor[NBUCK_MAX];   // histogram -> fill cursor -> bucket end
__device__ int g_start[NBUCK_MAX];    // bucket start offsets
__device__ int g_entries[NP_MAX];     // packed: pi | (po&31)<<20
__device__ int g_aux[CHUNK];          // per-chunk totals for scan
__device__ float g_sum[CH], g_sumsq[CH], g_scale[CH], g_shift[CH];

// ---------------------------------------------------------------------------
__global__ void zero_meta_kernel(int nbuck) {
    int i = blockIdx.x * blockDim.x + threadIdx.x;
    int stride = gridDim.x * blockDim.x;
    for (; i < nbuck; i += stride) g_cursor[i] = 0;
    if (blockIdx.x == 0 && threadIdx.x < CH) {
        g_sum[threadIdx.x] = 0.f;
        g_sumsq[threadIdx.x] = 0.f;
    }
}

// histogram: grid.y = k
__global__ void hist_kernel(const int* __restrict__ pout, int P, int K) {
    int p = blockIdx.x * blockDim.x + threadIdx.x;
    int k = blockIdx.y;
    if (p < P) {
        int po = pout[(size_t)k * P + p];
        atomicAdd(&g_cursor[(po >> 5) * K + k], 1);
    }
}

// per-chunk totals
__global__ __launch_bounds__(CHUNK) void chunk_reduce_kernel(int nbuck) {
    __shared__ int s[CHUNK];
    int t = threadIdx.x;
    int i = blockIdx.x * CHUNK + t;
    s[t] = (i < nbuck) ? g_cursor[i] : 0;
    __syncthreads();
    for (int o = CHUNK / 2; o > 0; o >>= 1) {
        if (t < o) s[t] += s[t + o];
        __syncthreads();
    }
    if (t == 0) g_aux[blockIdx.x] = s[0];
}

// exclusive scan of per-chunk totals (single block)
__global__ __launch_bounds__(CHUNK) void aux_scan_kernel(int nchunks) {
    __shared__ int s[CHUNK];
    int t = threadIdx.x;
    int v = (t < nchunks) ? g_aux[t] : 0;
    s[t] = v;
    __syncthreads();
    for (int o = 1; o < CHUNK; o <<= 1) {
        int x = (t >= o) ? s[t - o] : 0;
        __syncthreads();
        s[t] += x;
        __syncthreads();
    }
    if (t < nchunks) g_aux[t] = s[t] - v;  // exclusive
}

// per-chunk exclusive scan + chunk offset -> g_start, g_cursor
__global__ __launch_bounds__(CHUNK) void chunk_scan_kernel(int nbuck) {
    __shared__ int s[CHUNK];
    int t = threadIdx.x;
    int i = blockIdx.x * CHUNK + t;
    int v = (i < nbuck) ? g_cursor[i] : 0;
    s[t] = v;
    __syncthreads();
    for (int o = 1; o < CHUNK; o <<= 1) {
        int x = (t >= o) ? s[t - o] : 0;
        __syncthreads();
        s[t] += x;
        __syncthreads();
    }
    if (i < nbuck) {
        int excl = s[t] - v + g_aux[blockIdx.x];
        g_start[i] = excl;
        g_cursor[i] = excl;   // fill cursor starts at bucket start
    }
}

// scatter contributions into sorted entry array; grid.y = k
__global__ void fill_kernel(const int* __restrict__ pin,
                            const int* __restrict__ pout, int P, int K) {
    int p = blockIdx.x * blockDim.x + threadIdx.x;
    int k = blockIdx.y;
    if (p < P) {
        size_t idx = (size_t)k * P + p;
        int po = pout[idx];
        int pi = pin[idx];
        int slot = atomicAdd(&g_cursor[(po >> 5) * K + k], 1);
        g_entries[slot] = pi | ((po & 31) << 20);
    }
}

// ---------------------------------------------------------------------------
// Conv: warp owns rows [32w, 32w+32). For each k: weight column in FFMA2-packed
// regs, process bucket entries in batches of 32 (stage feat rows to smem,
// broadcast-read per entry, accumulate into smem acc via race-free RMW).
// Flush fused with BN stats partial sums.

#define CWARPS 4

__global__ __launch_bounds__(128) void conv_kernel(
    const float* __restrict__ feat,
    const float* __restrict__ weight,
    float* __restrict__ out,
    int K, int nwarp, int N)
{
    __shared__ float acc[CWARPS][RPW * CH];        // 16KB
    __shared__ ulonglong2 stg[CWARPS][32 * 8];     // 16KB
    __shared__ float ssum[CWARPS][CH];
    __shared__ float ssum2[CWARPS][CH];

    const int lane = threadIdx.x & 31;
    const int warp = threadIdx.x >> 5;
    const int w = blockIdx.x * CWARPS + warp;

    float* accw = acc[warp];
    ulonglong2* bw = stg[warp];

    if (w < nwarp) {
#pragma unroll
        for (int r = 0; r < RPW; r++) accw[r * CH + lane] = 0.f;

        for (int k = 0; k < K; k++) {
            int b = w * K + k;
            int s = g_start[b];
            int e = g_cursor[b];     // after fill, cursor == bucket end
            if (s == e) continue;

            // weight column for this lane, FFMA2-packed
            const float* wk = weight + (size_t)k * CH * CH;
            unsigned long long w2[CH / 2];
#pragma unroll
            for (int j = 0; j < CH / 2; j++) {
                float lo = wk[(2 * j) * CH + lane];
                float hi = wk[(2 * j + 1) * CH + lane];
                asm("mov.b64 %0, {%1, %2};" : "=l"(w2[j]) : "f"(lo), "f"(hi));
            }

            for (int base = s; base < e; base += 32) {
                int valid = e - base;
                if (valid > 32) valid = 32;
                int ent = 0;
                if (lane < valid) ent = g_entries[base + lane];
                int pi = ent & (N_MAX - 1);
                int row = (ent >> 20) & 31;

                if (lane < valid) {
                    const ulonglong2* frow = (const ulonglong2*)(feat + (size_t)pi * CH);
#pragma unroll
                    for (int i = 0; i < 8; i++)
                        bw[lane * 8 + ((i + lane) & 7)] = frow[i];
                }
                __syncwarp();

#pragma unroll 4
                for (int q = 0; q < valid; q++) {
                    unsigned long long acc0 = 0ull, acc1 = 0ull;
#pragma unroll
                    for (int i = 0; i < 8; i += 2) {
                        ulonglong2 a = bw[q * 8 + ((i + q) & 7)];
                        ulonglong2 c = bw[q * 8 + ((i + 1 + q) & 7)];
                        asm("fma.rn.f32x2 %0, %1, %2, %0;" : "+l"(acc0) : "l"(a.x), "l"(w2[2 * i + 0]));
                        asm("fma.rn.f32x2 %0, %1, %2, %0;" : "+l"(acc1) : "l"(a.y), "l"(w2[2 * i + 1]));
                        asm("fma.rn.f32x2 %0, %1, %2, %0;" : "+l"(acc0) : "l"(c.x), "l"(w2[2 * i + 2]));
                        asm("fma.rn.f32x2 %0, %1, %2, %0;" : "+l"(acc1) : "l"(c.y), "l"(w2[2 * i + 3]));
                    }
                    float a0lo, a0hi, a1lo, a1hi;
                    asm("mov.b64 {%0, %1}, %2;" : "=f"(a0lo), "=f"(a0hi) : "l"(acc0));
                    asm("mov.b64 {%0, %1}, %2;" : "=f"(a1lo), "=f"(a1hi) : "l"(acc1));
                    float accv = (a0lo + a1lo) + (a0hi + a1hi);

                    int rowq = __shfl_sync(0xffffffffu, row, q);
                    // race-free: lane=channel, sequential in q within the warp
                    accw[rowq * CH + lane] += accv;
                }
                __syncwarp();
            }
        }
    }

    // flush + fused BN stats partials
    float s = 0.f, s2 = 0.f;
    if (w < nwarp) {
        int rbase = w * RPW;
#pragma unroll 4
        for (int r = 0; r < RPW; r++) {
            int rg = rbase + r;
            if (rg >= N) break;
            float v = accw[r * CH + lane];
            out[(size_t)rg * CH + lane] = v;
            float l = (v >= 0.f) ? v : LRELU_SLOPE * v;
            s += l;
            s2 = fmaf(l, l, s2);
        }
    }
    ssum[warp][lane] = s;
    ssum2[warp][lane] = s2;
    __syncthreads();
    if (warp == 0) {
        float ts = 0.f, t2 = 0.f;
#pragma unroll
        for (int wi = 0; wi < CWARPS; wi++) { ts += ssum[wi][lane]; t2 += ssum2[wi][lane]; }
        atomicAdd(&g_sum[lane], ts);
        atomicAdd(&g_sumsq[lane], t2);
    }
}

// ---------------------------------------------------------------------------
__global__ void finalize_kernel(const float* __restrict__ gamma,
                                const float* __restrict__ beta,
                                float inv_n) {
    int l = threadIdx.x;
    float mean = g_sum[l] * inv_n;
    float var  = g_sumsq[l] * inv_n - mean * mean;
    float a = gamma[l] * rsqrtf(var + BN_EPS);
    g_scale[l] = a;
    g_shift[l] = fmaf(-mean, a, beta[l]);
}

// ---------------------------------------------------------------------------
__global__ __launch_bounds__(256) void norm_kernel(float4* __restrict__ out, int n4) {
    __shared__ float sc[CH], sh[CH];
    if (threadIdx.x < CH) { sc[threadIdx.x] = g_scale[threadIdx.x]; sh[threadIdx.x] = g_shift[threadIdx.x]; }
    __syncthreads();
    int i = blockIdx.x * blockDim.x + threadIdx.x;
    int stride = gridDim.x * blockDim.x;
    for (; i < n4; i += stride) {
        float4 v = out[i];
        int c = (i & 7) * 4;
        float x;
        x = (v.x >= 0.f) ? v.x : LRELU_SLOPE * v.x;  v.x = fmaf(x, sc[c + 0], sh[c + 0]);
        x = (v.y >= 0.f) ? v.y : LRELU_SLOPE * v.y;  v.y = fmaf(x, sc[c + 1], sh[c + 1]);
        x = (v.z >= 0.f) ? v.z : LRELU_SLOPE * v.z;  v.z = fmaf(x, sc[c + 2], sh[c + 2]);
        x = (v.w >= 0.f) ? v.w : LRELU_SLOPE * v.w;  v.w = fmaf(x, sc[c + 3], sh[c + 3]);
        out[i] = v;
    }
}

// ---------------------------------------------------------------------------
extern "C" void kernel_launch(void* const* d_in, const int* in_sizes, int n_in,
                              void* d_out, int out_size) {
    const float* feat   = (const float*)d_in[0];   // [N, 32]
    const float* weight = (const float*)d_in[1];   // [K, 32, 32]
    const float* gamma  = (const float*)d_in[2];   // [32]
    const float* beta   = (const float*)d_in[3];   // [32]
    const int*   pin    = (const int*)d_in[4];     // [K, P]
    const int*   pout   = (const int*)d_in[5];     // [K, P]
    float* out = (float*)d_out;

    const int N  = in_sizes[0] / CH;
    const int K  = in_sizes[1] / (CH * CH);
    const int P  = in_sizes[4] / K;
    const int nwarp   = (N + RPW - 1) / RPW;
    const int nbuck   = nwarp * K;
    const int nchunks = (nbuck + CHUNK - 1) / CHUNK;
    const int n4 = N * CH / 4;

    dim3 pgrid((P + 255) / 256, K);

    zero_meta_kernel<<<512, 256>>>(nbuck);
    hist_kernel<<<pgrid, 256>>>(pout, P, K);
    chunk_reduce_kernel<<<nchunks, CHUNK>>>(nbuck);
    aux_scan_kernel<<<1, CHUNK>>>(nchunks);
    chunk_scan_kernel<<<nchunks, CHUNK>>>(nbuck);
    fill_kernel<<<pgrid, 256>>>(pin, pout, P, K);
    conv_kernel<<<(nwarp + CWARPS - 1) / CWARPS, 128>>>(feat, weight, out, K, nwarp, N);
    finalize_kernel<<<1, 32>>>(gamma, beta, 1.0f / (float)N);
    norm_kernel<<<2048, 256>>>((float4*)out, n4);
}

// round 7
// speedup vs baseline: 1.2939x; 1.2939x over previous
#include <cuda_runtime.h>

// ConvLayer_6279242186805: submanifold sparse conv (K=27, P pairs/offset,
// Cin=Cout=32) + LeakyReLU + BatchNorm1d training-stats.
//
// R5: back to R2 structure (best). Conv gather uses cp.async double-buffered
// smem pipeline (batch b+1 streams while batch b computes). Zero kernel split
// into 3 launches so conv is pipeline launch index 3 (the one ncu captures).

#define LRELU_SLOPE 0.01f
#define BN_EPS 1e-5f
#define CH 32

__device__ float g_sum[CH];
__device__ float g_sumsq[CH];
__device__ float g_scale[CH];
__device__ float g_shift[CH];

// ---------------------------------------------------------------------------
__global__ void zero_half_kernel(float4* __restrict__ out, int n4) {
    int i = blockIdx.x * blockDim.x + threadIdx.x;
    int stride = gridDim.x * blockDim.x;
    float4 z = make_float4(0.f, 0.f, 0.f, 0.f);
    for (; i < n4; i += stride) out[i] = z;
}

__global__ void zero_stats_kernel() {
    if (threadIdx.x < CH) {
        g_sum[threadIdx.x] = 0.f;
        g_sumsq[threadIdx.x] = 0.f;
    }
}

// ---------------------------------------------------------------------------
// Conv: grid = (pair_chunks, K). Block = 128 threads = 4 warps.
// Warp: weight column of W[k] in FFMA2-packed regs (lane = out channel).
// Batches of 32 pairs; gathered rows stream into double-buffered smem via
// cp.async while the previous batch computes. Per pair: 8 broadcast LDS.128,
// 16 FFMA2, transpose via shfl, red.global.add.v4.f32 from lanes 0..7.

#define WARPS_PER_BLOCK 4
#define BATCH 32
#define BATCHES_PER_WARP 4
#define PAIRS_PER_BLOCK (WARPS_PER_BLOCK * BATCH * BATCHES_PER_WARP)  // 512

__device__ __forceinline__ unsigned smem_u32(const void* p) {
    return (unsigned)__cvta_generic_to_shared(p);
}

__global__ __launch_bounds__(128) void conv_kernel(
    const float* __restrict__ feat,
    const float* __restrict__ weight,
    const int*   __restrict__ pin,
    const int*   __restrict__ pout,
    float* __restrict__ out,
    int P)
{
    __shared__ ulonglong2 buf[WARPS_PER_BLOCK][2][BATCH * 8];  // 8KB per warp

    const int lane = threadIdx.x & 31;
    const int warp = threadIdx.x >> 5;
    const int k = blockIdx.y;

    // weight column for this lane, FFMA2-packed: w2[j] = {W[k][2j][lane], W[k][2j+1][lane]}
    const float* wk = weight + (size_t)k * CH * CH;
    unsigned long long w2[CH / 2];
#pragma unroll
    for (int j = 0; j < CH / 2; j++) {
        float lo = wk[(2 * j) * CH + lane];
        float hi = wk[(2 * j + 1) * CH + lane];
        asm("mov.b64 %0, {%1, %2};" : "=l"(w2[j]) : "f"(lo), "f"(hi));
    }

    const int* pin_k  = pin  + (size_t)k * P;
    const int* pout_k = pout + (size_t)k * P;

    const int base = blockIdx.x * PAIRS_PER_BLOCK + warp * (BATCH * BATCHES_PER_WARP);
    int nb = 0;
    if (base < P) {
        nb = (P - base + BATCH - 1) / BATCH;
        if (nb > BATCHES_PER_WARP) nb = BATCHES_PER_WARP;
    }

    // issue cp.async gather for batch b into buffer slot s; returns this lane's po
    auto issue = [&](int b, int s) -> int {
        int p0 = base + b * BATCH;
        int pi = 0, po = 0;
        if (lane < P - p0) {            // valid lanes (P-p0 may exceed 32; fine)
            pi = pin_k[p0 + lane];
            po = pout_k[p0 + lane];
        }
        const char* src = (const char*)(feat + (size_t)pi * CH);
        unsigned dst = smem_u32(&buf[warp][s][lane * 8]);
#pragma unroll
        for (int i = 0; i < 8; i++) {
            asm volatile("cp.async.cg.shared.global [%0], [%1], 16;"
                         :: "r"(dst + (((i + lane) & 7) * 16u)), "l"(src + i * 16)
                         : "memory");
        }
        asm volatile("cp.async.commit_group;" ::: "memory");
        return po;
    };

    int po_cur = 0, po_next = 0;
    if (nb > 0) po_cur = issue(0, 0);

    for (int b = 0; b < nb; b++) {
        if (b + 1 < nb) {
            po_next = issue(b + 1, (b + 1) & 1);
            asm volatile("cp.async.wait_group 1;" ::: "memory");
        } else {
            asm volatile("cp.async.wait_group 0;" ::: "memory");
        }
        __syncwarp();

        int p0 = base + b * BATCH;
        int valid = P - p0;
        if (valid > BATCH) valid = BATCH;
        const ulonglong2* bw = buf[warp][b & 1];

#pragma unroll 4
        for (int q = 0; q < valid; q++) {
            unsigned long long acc0 = 0ull, acc1 = 0ull;
#pragma unroll
            for (int i = 0; i < 8; i += 2) {
                ulonglong2 a = bw[q * 8 + ((i + q) & 7)];
                ulonglong2 c = bw[q * 8 + ((i + 1 + q) & 7)];
                asm("fma.rn.f32x2 %0, %1, %2, %0;" : "+l"(acc0) : "l"(a.x), "l"(w2[2 * i + 0]));
                asm("fma.rn.f32x2 %0, %1, %2, %0;" : "+l"(acc1) : "l"(a.y), "l"(w2[2 * i + 1]));
                asm("fma.rn.f32x2 %0, %1, %2, %0;" : "+l"(acc0) : "l"(c.x), "l"(w2[2 * i + 2]));
                asm("fma.rn.f32x2 %0, %1, %2, %0;" : "+l"(acc1) : "l"(c.y), "l"(w2[2 * i + 3]));
            }
            float a0lo, a0hi, a1lo, a1hi;
            asm("mov.b64 {%0, %1}, %2;" : "=f"(a0lo), "=f"(a0hi) : "l"(acc0));
            asm("mov.b64 {%0, %1}, %2;" : "=f"(a1lo), "=f"(a1hi) : "l"(acc1));
            float acc = (a0lo + a1lo) + (a0hi + a1hi);

            int poq = __shfl_sync(0xffffffffu, po_cur, q);
            int src = (lane & 7) * 4;
            float4 v;
            v.x = __shfl_sync(0xffffffffu, acc, src + 0);
            v.y = __shfl_sync(0xffffffffu, acc, src + 1);
            v.z = __shfl_sync(0xffffffffu, acc, src + 2);
            v.w = __shfl_sync(0xffffffffu, acc, src + 3);
            if (lane < 8) {
                float* dst = out + (size_t)poq * CH + lane * 4;
                asm volatile("red.global.add.v4.f32 [%0], {%1,%2,%3,%4};"
                             :: "l"(dst), "f"(v.x), "f"(v.y), "f"(v.z), "f"(v.w)
                             : "memory");
            }
        }
        po_cur = po_next;
        __syncwarp();   // buffer (b&1) may be rewritten by issue() next iteration
    }
}

// ---------------------------------------------------------------------------
__global__ __launch_bounds__(256) void stats_kernel(const float* __restrict__ x, int n) {
    int tid = blockIdx.x * blockDim.x + threadIdx.x;
    int stride = gridDim.x * blockDim.x;
    float s = 0.f, s2 = 0.f;
    for (int i = tid; i < n; i += stride) {
        float v = x[i];
        v = (v >= 0.f) ? v : LRELU_SLOPE * v;
        s += v;
        s2 = fmaf(v, v, s2);
    }
    __shared__ float ss[8][CH];
    __shared__ float ss2[8][CH];
    int lane = threadIdx.x & 31, warp = threadIdx.x >> 5;
    ss[warp][lane] = s;
    ss2[warp][lane] = s2;
    __syncthreads();
    if (warp == 0) {
        float ts = 0.f, t2 = 0.f;
#pragma unroll
        for (int wi = 0; wi < 8; wi++) { ts += ss[wi][lane]; t2 += ss2[wi][lane]; }
        atomicAdd(&g_sum[lane], ts);
        atomicAdd(&g_sumsq[lane], t2);
    }
}

// ---------------------------------------------------------------------------
__global__ void finalize_kernel(const float* __restrict__ gamma,
                                const float* __restrict__ beta,
                                float inv_n) {
    int l = threadIdx.x;
    float mean = g_sum[l] * inv_n;
    float var  = g_sumsq[l] * inv_n - mean * mean;
    float a = gamma[l] * rsqrtf(var + BN_EPS);
    g_scale[l] = a;
    g_shift[l] = fmaf(-mean, a, beta[l]);
}

// ---------------------------------------------------------------------------
__global__ __launch_bounds__(256) void norm_kernel(float4* __restrict__ out, int n4) {
    __shared__ float sc[CH], sh[CH];
    if (threadIdx.x < CH) { sc[threadIdx.x] = g_scale[threadIdx.x]; sh[threadIdx.x] = g_shift[threadIdx.x]; }
    __syncthreads();
    int i = blockIdx.x * blockDim.x + threadIdx.x;
    int stride = gridDim.x * blockDim.x;
    for (; i < n4; i += stride) {
        float4 v = out[i];
        int c = (i & 7) * 4;
        float x;
        x = (v.x >= 0.f) ? v.x : LRELU_SLOPE * v.x;  v.x = fmaf(x, sc[c + 0], sh[c + 0]);
        x = (v.y >= 0.f) ? v.y : LRELU_SLOPE * v.y;  v.y = fmaf(x, sc[c + 1], sh[c + 1]);
        x = (v.z >= 0.f) ? v.z : LRELU_SLOPE * v.z;  v.z = fmaf(x, sc[c + 2], sh[c + 2]);
        x = (v.w >= 0.f) ? v.w : LRELU_SLOPE * v.w;  v.w = fmaf(x, sc[c + 3], sh[c + 3]);
        out[i] = v;
    }
}

// ---------------------------------------------------------------------------
extern "C" void kernel_launch(void* const* d_in, const int* in_sizes, int n_in,
                              void* d_out, int out_size) {
    const float* feat   = (const float*)d_in[0];   // [N, 32]
    const float* weight = (const float*)d_in[1];   // [K, 32, 32]
    const float* gamma  = (const float*)d_in[2];   // [32]
    const float* beta   = (const float*)d_in[3];   // [32]
    const int*   pin    = (const int*)d_in[4];     // [K, P]
    const int*   pout   = (const int*)d_in[5];     // [K, P]
    float* out = (float*)d_out;

    const int N  = in_sizes[0] / CH;
    const int K  = in_sizes[1] / (CH * CH);
    const int P  = in_sizes[4] / K;
    const int n  = N * CH;
    const int n4 = n / 4;
    const int h4 = n4 / 2;

    // launches 0..2: zeroing (split so conv is launch index 3 -> gets profiled)
    zero_half_kernel<<<1024, 256>>>((float4*)out, h4);
    zero_half_kernel<<<1024, 256>>>((float4*)out + h4, n4 - h4);
    zero_stats_kernel<<<1, 32>>>();

    // launch 3: conv scatter-add
    dim3 grid((P + PAIRS_PER_BLOCK - 1) / PAIRS_PER_BLOCK, K);
    conv_kernel<<<grid, 128>>>(feat, weight, pin, pout, out, P);

    // launches 4..6
    stats_kernel<<<1184, 256>>>(out, n);
    finalize_kernel<<<1, 32>>>(gamma, beta, 1.0f / (float)N);
    norm_kernel<<<2048, 256>>>((float4*)out, n4);
}